// round 16
// baseline (speedup 1.0000x reference)
#include <cuda_runtime.h>
#include <math.h>

#define B_    32
#define H_    8
#define E_    64
#define M_    64
#define L_    1024
#define DOUT_ 64
#define HE    512
#define M2    128

// ---------------- device scratch ----------------
__device__ float d_QfP[2][B_ * HE * M2];
__device__ float d_KfP[2][B_ * HE * M2];
__device__ float d_KV[512 * 2 * 2048];
__device__ float d_WTr[8 * 64 * 64 * 64];
__device__ float d_WTi[8 * 64 * 64 * 64];
__device__ float d_X2T[128 * 16384];
__device__ float2 d_sc[L_];

// radix-8 forward twiddles [z][part][u][128 slots]
__device__ float d_T8m[2][2][128][128];
__device__ float d_T8s[2][2][128][128];
__device__ int d_m8v[2][128];
__device__ int d_pgA8v[2][32];
__device__ int d_pgB8v[2][32];
__device__ int d_p2s8[2][64];
__device__ int d_Spad8[2];

// radix-8 inverse tables [slot][u<128]
__device__ float d_IAr[64 * 128], d_IAi[64 * 128];
__device__ float d_IBr[64 * 128], d_IBi[64 * 128];
__device__ int d_slotm_q[64];
__device__ int d_pos2slot_q[64];
__device__ int d_bnd_q[4];

__device__ __forceinline__ float ftanh(float x) {
    float t = __expf(2.0f * x);
    return 1.0f - 2.0f / (t + 1.0f);
}

// ---------------- setup1: sc LUT + both metas (one launch) -----------------
__global__ void setup1_k(const int* __restrict__ iq, const int* __restrict__ ikv) {
    __shared__ int mA[64], keys[64], s2p[128];
    const int bx = blockIdx.x, tid = threadIdx.x;
    if (bx < 4) {
        int t = bx * 256 + tid;
        const double C = 6.283185307179586476925286766559 / (double)L_;
        double th = C * (double)t;
        d_sc[t] = make_float2((float)cos(th), (float)sin(th));
        return;
    }
    if (bx == 4) {
        if (tid < 64) mA[tid] = iq[tid];
        __syncthreads();
        if (tid < 64) {
            int m = mA[tid], c = m & 7;
            int cp = (c <= 4) ? c : 8 - c;
            int rank = (cp == 0) ? 0 : (cp == 4) ? 1 : (cp == 1) ? 2 : (cp == 2) ? 3 : 4;
            keys[tid] = rank * 64 + tid;
        }
        __syncthreads();
        if (tid < 64) {
            int key = keys[tid], slot = 0;
            for (int t = 0; t < 64; t++) slot += (keys[t] < key);
            d_slotm_q[slot] = mA[tid];
            d_pos2slot_q[tid] = slot;
        }
        __syncthreads();
        if (tid == 0) {
            int cnt[5] = {0, 0, 0, 0, 0};
            for (int t = 0; t < 64; t++) {
                int cc = mA[t] & 7;
                int cpp = (cc <= 4) ? cc : 8 - cc;
                int rr = (cpp == 0) ? 0 : (cpp == 4) ? 1 : (cpp == 1) ? 2 : (cpp == 2) ? 3 : 4;
                cnt[rr]++;
            }
            d_bnd_q[0] = cnt[0];
            d_bnd_q[1] = cnt[0] + cnt[1];
            d_bnd_q[2] = cnt[0] + cnt[1] + cnt[2];
            d_bnd_q[3] = cnt[0] + cnt[1] + cnt[2] + cnt[3];
        }
        return;
    }
    {
        int z = bx - 5;
        const int* ix = z ? ikv : iq;
        if (tid < 64) mA[tid] = ix[tid];
        __syncthreads();
        if (tid == 0) {
            int cS[64], cnt[5] = {0,0,0,0,0};
            for (int t = 0; t < 64; t++) {
                int c = mA[t] & 7;
                int cp = (c <= 4) ? c : 8 - c;
                cS[t] = cp; cnt[cp]++;
            }
            int pb[5], pe[5], acc = 0;
            for (int c = 0; c < 5; c++) { pb[c] = acc; acc += (cnt[c] + 3) & ~3; pe[c] = acc; }
            d_Spad8[z] = acc;
            for (int s = 0; s < 128; s++) { d_m8v[z][s] = -1; s2p[s] = -1; }
            int fill[5] = {0,0,0,0,0};
            for (int t = 0; t < 64; t++) {
                int s = pb[cS[t]] + fill[cS[t]]++;
                d_m8v[z][s] = mA[t];
                s2p[s] = t;
            }
            const int pAt[5] = {0, 2, 4, 6, 1};
            const int pBt[5] = {0, 3, 5, 7, 1};
            for (int g = 0; g < 32; g++) {
                int s0 = g * 4, A = 0, Bp = 0;
                for (int c = 0; c < 5; c++)
                    if (cnt[c] > 0 && s0 >= pb[c] && s0 < pe[c]) { A = pAt[c]; Bp = pBt[c]; }
                d_pgA8v[z][g] = A;
                d_pgB8v[z][g] = Bp;
            }
            for (int s = 0; s < 128; s++)
                if (s2p[s] >= 0) d_p2s8[z][s2p[s]] = s;
        }
    }
}

// ---------------- setup2: twiddle tables + w transpose (one launch) ---------
__global__ __launch_bounds__(256) void setup2_k(const float* __restrict__ wr_g,
                                                const float* __restrict__ wi_g) {
    __shared__ float tile[32][33];
    const int bx = blockIdx.x, tid = threadIdx.x;
    if (bx < 32) {
        int idx = bx * 256 + tid;
        int j = idx >> 7, u = idx & 127;
        int m = d_slotm_q[j];
        float2 cs = d_sc[(m * u) & (L_ - 1)];
        float g = ((m == 0) || (2 * m == L_)) ? (1.0f / L_) : (2.0f / L_);
        int c = m & 7;
        float sg = (c < 4) ? 1.f : -1.f;
        bool noB = (c == 0) || (c == 4);
        d_IAr[j * 128 + u] =  g * cs.x;
        d_IAi[j * 128 + u] = -g * cs.y;
        d_IBr[j * 128 + u] = noB ? 0.f : (sg * g * cs.y);
        d_IBi[j * 128 + u] = noB ? 0.f : (sg * g * cs.x);
        return;
    }
    if (bx < 160) {
        int r = bx - 32;
        int z = r >> 6;
        int idx = (r & 63) * 256 + tid;
        int u = idx >> 7, s = idx & 127;
        int m = d_m8v[z][s];
        float tmr = 0.f, tsr = 0.f, tmi = 0.f, tsi = 0.f;
        if (m >= 0) {
            float2 cssn = d_sc[(m * u) & (L_ - 1)];
            int c = m & 7;
            float sg = (c <= 4) ? 1.f : -1.f;
            bool noB = (c == 0) || (c == 4);
            tmr = cssn.x;
            tsr = noB ? 0.f : (sg * cssn.y);
            tmi = -cssn.y;
            tsi = noB ? 0.f : (sg * cssn.x);
        }
        d_T8m[z][0][u][s] = tmr;
        d_T8s[z][0][u][s] = tsr;
        d_T8m[z][1][u][s] = tmi;
        d_T8s[z][1][u][s] = tsi;
        return;
    }
    {
        int rr = bx - 160;
        const int ot = (rr & 1) * 32;
        const int mt = ((rr >> 1) & 1) * 32;
        const int e  = (rr >> 2) & 63;
        const int h  = rr >> 8;
        const int r  = tid >> 3;
        const int c4 = (tid & 7) * 4;
        for (int z = 0; z < 2; z++) {
            const float* src = z ? wi_g : wr_g;
            float* dst = z ? d_WTi : d_WTr;
            float4 v = *(const float4*)&src[((size_t)(h * 64 + e) * 64 + ot + r) * 64 + mt + c4];
            tile[r][c4 + 0] = v.x; tile[r][c4 + 1] = v.y;
            tile[r][c4 + 2] = v.z; tile[r][c4 + 3] = v.w;
            __syncthreads();
            float4 o;
            o.x = tile[c4 + 0][r]; o.y = tile[c4 + 1][r];
            o.z = tile[c4 + 2][r]; o.w = tile[c4 + 3][r];
            *(float4*)&dst[((size_t)(h * 64 + mt + r) * 64 + e) * 64 + ot + c4] = o;
            __syncthreads();
        }
    }
}

// ---------------- forward: radix-8 folded DFT, 256 thr, 4x4 tile -----------
#define PLPAD 68
#define PLBUF (8 * 8 * PLPAD)
__global__ __launch_bounds__(256, 3) void dft8m_k(const float* __restrict__ qg,
                                                  const float* __restrict__ kg) {
    const int bx   = blockIdx.x;
    const int tile = bx & 1;
    const int us   = (bx >> 1) & 1;
    const int heT  = bx >> 2;
    const int b    = blockIdx.y;
    const int zin  = blockIdx.z;
    if (tile * 64 >= d_Spad8[zin]) return;

    extern __shared__ float sm[];
    float* PL = sm;
    float* TW = sm + 2 * PLBUF;

    const float* __restrict__ x = zin ? kg : qg;
    float* outp = zin ? d_KfP[us] : d_QfP[us];
    const int he0 = heT * 64;
    const int tid = threadIdx.x;
    const int g   = tid & 15;
    const int cx  = g * 4;
    const int ry  = ((tid >> 4) & 15) * 4;
    const int pgA = d_pgA8v[zin][tile * 16 + g];
    const int pgB = d_pgB8v[zin][tile * 16 + g];
    const float* xb = x + (size_t)b * (L_ * HE) + he0;

    float accR[4][4], accI[4][4];
    #pragma unroll
    for (int i = 0; i < 4; i++)
        #pragma unroll
        for (int j = 0; j < 4; j++) { accR[i][j] = 0.f; accI[i][j] = 0.f; }

    auto load = [&](int ks, int buf) {
        const int u0 = us * 64 + ks * 8;
        if (tid < 128) {
            float* plb = PL + buf * PLBUF;
            const int ul = tid >> 4;
            const int c4 = (tid & 15) * 4;
            const float* p = xb + (size_t)(u0 + ul) * HE + c4;
            float4 xs[8];
            #pragma unroll
            for (int pp = 0; pp < 8; pp++)
                xs[pp] = *(const float4*)(p + (size_t)pp * 128 * HE);
            float4 pl8[8];
            const float KK = 0.70710678118654752440f;
            #pragma unroll
            for (int q = 0; q < 4; q++) {
                float x0 = (&xs[0].x)[q], x1 = (&xs[1].x)[q], x2 = (&xs[2].x)[q], x3 = (&xs[3].x)[q];
                float x4 = (&xs[4].x)[q], x5 = (&xs[5].x)[q], x6 = (&xs[6].x)[q], x7 = (&xs[7].x)[q];
                float e0 = x0 + x4, e1 = x1 + x5, e2 = x2 + x6, e3 = x3 + x7;
                float o0 = x0 - x4, o1 = x1 - x5, o2 = x2 - x6, o3 = x3 - x7;
                float g0 = e0 + e2, g1 = e1 + e3;
                float t1 = o1 - o3, t2 = o1 + o3;
                float kt1 = KK * t1, kt2 = KK * t2;
                (&pl8[0].x)[q] = g0 + g1;
                (&pl8[1].x)[q] = g0 - g1;
                (&pl8[2].x)[q] = o0 + kt1;
                (&pl8[3].x)[q] = -kt2 - o2;
                (&pl8[4].x)[q] = e0 - e2;
                (&pl8[5].x)[q] = e3 - e1;
                (&pl8[6].x)[q] = o0 - kt1;
                (&pl8[7].x)[q] = o2 - kt2;
            }
            #pragma unroll
            for (int pl = 0; pl < 8; pl++)
                *(float4*)&plb[(ul * 8 + pl) * PLPAD + c4] = pl8[pl];
        } else {
            float* twb = TW + buf * 2048;
            #pragma unroll
            for (int r = 0; r < 4; r++) {
                int f = (tid - 128) + 128 * r;
                int uu  = f >> 6;
                int wh  = (f >> 4) & 3;
                int c4t = (f & 15) * 4;
                const float* srcT;
                if (wh == 0)      srcT = &d_T8m[zin][0][u0 + uu][tile * 64];
                else if (wh == 1) srcT = &d_T8s[zin][0][u0 + uu][tile * 64];
                else if (wh == 2) srcT = &d_T8m[zin][1][u0 + uu][tile * 64];
                else              srcT = &d_T8s[zin][1][u0 + uu][tile * 64];
                *(float4*)&twb[(uu * 4 + wh) * 64 + c4t] = *(const float4*)(srcT + c4t);
            }
        }
    };

    load(0, 0);
    __syncthreads();
    #pragma unroll 1
    for (int ks = 0; ks < 8; ks++) {
        int buf = ks & 1;
        if (ks + 1 < 8) load(ks + 1, buf ^ 1);
        float* plb = PL + buf * PLBUF;
        float* twb = TW + buf * 2048;
        #pragma unroll
        for (int u = 0; u < 8; u++) {
            float av[4], bw[4], tmr[4], tsr[4], tmi[4], tsi[4];
            *(float4*)&av[0] = *(float4*)&plb[(u * 8 + pgA) * PLPAD + ry];
            *(float4*)&bw[0] = *(float4*)&plb[(u * 8 + pgB) * PLPAD + ry];
            *(float4*)&tmr[0] = *(float4*)&twb[(u * 4 + 0) * 64 + cx];
            *(float4*)&tsr[0] = *(float4*)&twb[(u * 4 + 1) * 64 + cx];
            *(float4*)&tmi[0] = *(float4*)&twb[(u * 4 + 2) * 64 + cx];
            *(float4*)&tsi[0] = *(float4*)&twb[(u * 4 + 3) * 64 + cx];
            #pragma unroll
            for (int i = 0; i < 4; i++)
                #pragma unroll
                for (int j = 0; j < 4; j++) {
                    accR[i][j] += av[i] * tmr[j] + bw[i] * tsr[j];
                    accI[i][j] += av[i] * tmi[j] + bw[i] * tsi[j];
                }
        }
        __syncthreads();
    }

    float* OUT = sm;
    #pragma unroll
    for (int i = 0; i < 4; i++) {
        int row = ry + i;
        int rsw = (row >> 2) & 2;
        #pragma unroll
        for (int j = 0; j < 4; j++) {
            int cR = cx + j;
            OUT[row * 128 + (cR ^ ((cR >> 5) & 1) ^ rsw)] = accR[i][j];
            int cI = 64 + cx + j;
            OUT[row * 128 + (cI ^ ((cI >> 5) & 1) ^ rsw)] = accI[i][j];
        }
    }
    __syncthreads();
    {
        int c = tid & 127;
        int rh = tid >> 7;
        int sl = d_p2s8[zin][c & 63];
        if ((sl >> 6) == tile) {
            int srcCol = (c < 64) ? (sl & 63) : (64 + (sl & 63));
            srcCol ^= (srcCol >> 5) & 1;
            float* dstc = outp + ((size_t)b * HE + he0 + rh * 32) * M2 + c;
            #pragma unroll 8
            for (int r = 0; r < 32; r++) {
                int row = rh * 32 + r;
                dstc[(size_t)r * M2] = OUT[row * 128 + (srcCol ^ ((row >> 2) & 2))];
            }
        }
    }
}

// ---------------- stage2+3: qk GEMM + tanh + kv GEMM (512 thr, fused) ------
__global__ __launch_bounds__(512) void stage23_k() {
    extern __shared__ float sm[];
    float* Qs  = sm;            // [64][128]
    float* Ks  = sm + 8192;
    float* qkr = sm;            // alias over Qs (after sync)
    float* qki = sm + 4096;

    const int h = blockIdx.x, b = blockIdx.y;
    const int tid = threadIdx.x;

    const size_t off4 = (((size_t)b * HE + h * E_) * M2) / 4;
    for (int i = tid; i < E_ * M2 / 4; i += 512) {
        float4 a0 = ((const float4*)d_QfP[0])[off4 + i];
        float4 a1 = ((const float4*)d_QfP[1])[off4 + i];
        ((float4*)Qs)[i] = make_float4(a0.x + a1.x, a0.y + a1.y,
                                       a0.z + a1.z, a0.w + a1.w);
        float4 c0 = ((const float4*)d_KfP[0])[off4 + i];
        float4 c1 = ((const float4*)d_KfP[1])[off4 + i];
        ((float4*)Ks)[i] = make_float4(c0.x + c1.x, c0.y + c1.y,
                                       c0.z + c1.z, c0.w + c1.w);
    }
    __syncthreads();

    const int x0 = (tid & 15) * 4;
    const int yg = tid >> 4;         // 0..31
    {
        int y0 = yg * 2;
        float ar[2][4], ai[2][4];
        #pragma unroll
        for (int yy = 0; yy < 2; yy++)
            #pragma unroll
            for (int xx = 0; xx < 4; xx++) { ar[yy][xx] = 0.f; ai[yy][xx] = 0.f; }
        #pragma unroll 4
        for (int e = 0; e < 64; e++) {
            float4 q4r = *(float4*)&Qs[e * 128 + x0];
            float4 q4i = *(float4*)&Qs[e * 128 + 64 + x0];
            float2 k2r = *(float2*)&Ks[e * 128 + y0];
            float2 k2i = *(float2*)&Ks[e * 128 + 64 + y0];
            float qrv[4] = {q4r.x,q4r.y,q4r.z,q4r.w};
            float qiv[4] = {q4i.x,q4i.y,q4i.z,q4i.w};
            float krv[2] = {k2r.x,k2r.y};
            float kiv[2] = {k2i.x,k2i.y};
            #pragma unroll
            for (int yy = 0; yy < 2; yy++)
                #pragma unroll
                for (int xx = 0; xx < 4; xx++) {
                    ar[yy][xx] += qrv[xx]*krv[yy] - qiv[xx]*kiv[yy];
                    ai[yy][xx] += qrv[xx]*kiv[yy] + qiv[xx]*krv[yy];
                }
        }
        __syncthreads();
        #pragma unroll
        for (int yy = 0; yy < 2; yy++)
            #pragma unroll
            for (int xx = 0; xx < 4; xx++) {
                qkr[(y0 + yy) * 64 + x0 + xx] = ftanh(ar[yy][xx]);
                qki[(y0 + yy) * 64 + x0 + xx] = ftanh(ai[yy][xx]);
            }
    }
    __syncthreads();

    {
        int e0 = yg * 2;
        float cr[2][4], ci[2][4];
        #pragma unroll
        for (int ee = 0; ee < 2; ee++)
            #pragma unroll
            for (int xx = 0; xx < 4; xx++) { cr[ee][xx] = 0.f; ci[ee][xx] = 0.f; }
        #pragma unroll 4
        for (int y = 0; y < 64; y++) {
            float4 q4r = *(float4*)&qkr[y * 64 + x0];
            float4 q4i = *(float4*)&qki[y * 64 + x0];
            float qrv[4] = {q4r.x,q4r.y,q4r.z,q4r.w};
            float qiv[4] = {q4i.x,q4i.y,q4i.z,q4i.w};
            float krv[2], kiv[2];
            #pragma unroll
            for (int ee = 0; ee < 2; ee++) {
                krv[ee] = Ks[(e0 + ee) * 128 + y];
                kiv[ee] = Ks[(e0 + ee) * 128 + 64 + y];
            }
            #pragma unroll
            for (int ee = 0; ee < 2; ee++)
                #pragma unroll
                for (int xx = 0; xx < 4; xx++) {
                    cr[ee][xx] += qrv[xx]*krv[ee] - qiv[xx]*kiv[ee];
                    ci[ee][xx] += qrv[xx]*kiv[ee] + qiv[xx]*krv[ee];
                }
        }
        #pragma unroll
        for (int xx = 0; xx < 4; xx++) {
            size_t base = ((size_t)(h * 64 + x0 + xx) * 2) * 2048 + b * 64 + e0;
            *(float2*)&d_KV[base]        = make_float2(cr[0][xx], cr[1][xx]);
            *(float2*)&d_KV[base + 2048] = make_float2(ci[0][xx], ci[1][xx]);
        }
    }
}

// ---------------- stage4: per-(h,mode) pointwise complex GEMM --------------
__global__ __launch_bounds__(128) void xw_k() {
    extern __shared__ float sm[];
    float* kvS = sm;         // [e][c][b]
    float* wS  = sm + 4096;  // [e][c][o]
    const int x = blockIdx.x, h = blockIdx.y;
    const int tid = threadIdx.x;

    {
        const float4* kb = (const float4*)(d_KV + ((size_t)(h * 64 + x) * 2) * 2048);
        #pragma unroll
        for (int r = 0; r < 8; r++) {
            int idx4 = tid + 128 * r;
            float4 v = kb[idx4];
            int e4 = idx4 & 15, bb = (idx4 >> 4) & 31, c = idx4 >> 9;
            #pragma unroll
            for (int j = 0; j < 4; j++)
                kvS[((e4 * 4 + j) * 2 + c) * 32 + bb] = (&v.x)[j];
        }
        const float4* wrb = (const float4*)(d_WTr + (size_t)(h * 64 + x) * 4096);
        const float4* wib = (const float4*)(d_WTi + (size_t)(h * 64 + x) * 4096);
        #pragma unroll
        for (int r = 0; r < 8; r++) {
            int idx4 = tid + 128 * r;
            int e = idx4 >> 4, o4 = idx4 & 15;
            *(float4*)&wS[(e * 2 + 0) * 64 + o4 * 4] = wrb[idx4];
            *(float4*)&wS[(e * 2 + 1) * 64 + o4 * 4] = wib[idx4];
        }
    }
    __syncthreads();

    const int b0 = (tid >> 4) * 4;
    const int o0 = (tid & 15) * 4;
    float cr[4][4], ci[4][4];
    #pragma unroll
    for (int i = 0; i < 4; i++)
        #pragma unroll
        for (int j = 0; j < 4; j++) { cr[i][j] = 0.f; ci[i][j] = 0.f; }

    #pragma unroll 4
    for (int e = 0; e < 64; e++) {
        float4 kr4 = *(float4*)&kvS[(e * 2 + 0) * 32 + b0];
        float4 ki4 = *(float4*)&kvS[(e * 2 + 1) * 32 + b0];
        float4 wr4 = *(float4*)&wS[(e * 2 + 0) * 64 + o0];
        float4 wi4 = *(float4*)&wS[(e * 2 + 1) * 64 + o0];
        float kr[4] = {kr4.x,kr4.y,kr4.z,kr4.w};
        float ki[4] = {ki4.x,ki4.y,ki4.z,ki4.w};
        float wr[4] = {wr4.x,wr4.y,wr4.z,wr4.w};
        float wi[4] = {wi4.x,wi4.y,wi4.z,wi4.w};
        #pragma unroll
        for (int i = 0; i < 4; i++)
            #pragma unroll
            for (int j = 0; j < 4; j++) {
                cr[i][j] += kr[i]*wr[j] - ki[i]*wi[j];
                ci[i][j] += kr[i]*wi[j] + ki[i]*wr[j];
            }
    }
    __syncthreads();

    const float S = 1.0f / 262144.0f;
    #pragma unroll
    for (int i = 0; i < 4; i++) {
        *(float4*)&wS[(0 * 32 + b0 + i) * 64 + o0] =
            make_float4(cr[i][0]*S, cr[i][1]*S, cr[i][2]*S, cr[i][3]*S);
        *(float4*)&wS[(1 * 32 + b0 + i) * 64 + o0] =
            make_float4(ci[i][0]*S, ci[i][1]*S, ci[i][2]*S, ci[i][3]*S);
    }
    __syncthreads();

    int slot = d_pos2slot_q[x];
    #pragma unroll
    for (int r = 0; r < 8; r++) {
        int idx4 = tid + 128 * r;
        int c = idx4 >> 9, bb = (idx4 >> 4) & 31, o4 = idx4 & 15;
        *(float4*)&d_X2T[(size_t)(2 * slot + c) * 16384 + (bb * 8 + h) * 64 + o4 * 4] =
            ((float4*)wS)[idx4];
    }
}

// ---------------- inverse: radix-8 folded irfft (32 rows/block) -------------
__global__ __launch_bounds__(256) void inv8_k(float* __restrict__ outp) {
    extern __shared__ float sm[];
    float* Ys = sm;              // [32 rows][128] 16KB
    float* Ar = sm + 4096;       // [64 slots][32 u] 8KB
    float* Ai = sm + 6144;
    float* Br = sm + 8192;
    float* Bi = sm + 10240;      // total 12288 floats = 48KB
    const int u0 = blockIdx.x * 32;
    const int r0 = blockIdx.y * 32;
    const int tid = threadIdx.x;

    for (int i = tid; i < 1024; i += 256) {
        int p = i >> 3, r4 = (i & 7) * 4;
        float4 v = *(const float4*)&d_X2T[(size_t)p * 16384 + r0 + r4];
        Ys[(r4 + 0) * 128 + p] = v.x;
        Ys[(r4 + 1) * 128 + p] = v.y;
        Ys[(r4 + 2) * 128 + p] = v.z;
        Ys[(r4 + 3) * 128 + p] = v.w;
    }
    for (int i = tid; i < 512; i += 256) {
        int s = i >> 3, f = (i & 7) * 4;
        *(float4*)&Ar[s * 32 + f] = *(const float4*)&d_IAr[s * 128 + u0 + f];
        *(float4*)&Ai[s * 32 + f] = *(const float4*)&d_IAi[s * 128 + u0 + f];
        *(float4*)&Br[s * 32 + f] = *(const float4*)&d_IBr[s * 128 + u0 + f];
        *(float4*)&Bi[s * 32 + f] = *(const float4*)&d_IBi[s * 128 + u0 + f];
    }
    __syncthreads();

    const int rr = (tid >> 4) * 2;     // 16 groups x 2 rows = 32 rows
    const int uu = (tid & 15) * 2;
    float A0[2][2] = {}, A4[2][2] = {};
    float A1[2][2] = {}, B1[2][2] = {};
    float A2[2][2] = {}, B2[2][2] = {};
    float A3[2][2] = {}, B3[2][2] = {};

    const int n0 = d_bnd_q[0], n4 = d_bnd_q[1], n1 = d_bnd_q[2], n2 = d_bnd_q[3];

#define IACC_A(S, A) { \
    float2 a2 = *(float2*)&Ar[(S) * 32 + uu]; \
    float2 i2 = *(float2*)&Ai[(S) * 32 + uu]; \
    _Pragma("unroll") \
    for (int r_ = 0; r_ < 2; r_++) { \
        float2 y = *(float2*)&Ys[(rr + r_) * 128 + 2 * (S)]; \
        A[r_][0] += y.x * a2.x + y.y * i2.x; \
        A[r_][1] += y.x * a2.y + y.y * i2.y; \
    } }

#define IACC_AB(S, A, Bm) { \
    float2 a2 = *(float2*)&Ar[(S) * 32 + uu]; \
    float2 i2 = *(float2*)&Ai[(S) * 32 + uu]; \
    float2 b2 = *(float2*)&Br[(S) * 32 + uu]; \
    float2 c2 = *(float2*)&Bi[(S) * 32 + uu]; \
    _Pragma("unroll") \
    for (int r_ = 0; r_ < 2; r_++) { \
        float2 y = *(float2*)&Ys[(rr + r_) * 128 + 2 * (S)]; \
        A[r_][0]  += y.x * a2.x + y.y * i2.x; \
        A[r_][1]  += y.x * a2.y + y.y * i2.y; \
        Bm[r_][0] += y.x * b2.x + y.y * c2.x; \
        Bm[r_][1] += y.x * b2.y + y.y * c2.y; \
    } }

    for (int s = 0;  s < n0; s++) IACC_A(s, A0);
    for (int s = n0; s < n4; s++) IACC_A(s, A4);
    for (int s = n4; s < n1; s++) IACC_AB(s, A1, B1);
    for (int s = n1; s < n2; s++) IACC_AB(s, A2, B2);
    for (int s = n2; s < 64; s++) IACC_AB(s, A3, B3);

#undef IACC_A
#undef IACC_AB

    const float K = 0.70710678118654752440f;
    #pragma unroll
    for (int r_ = 0; r_ < 2; r_++) {
        float ov[8][2];
        #pragma unroll
        for (int u_ = 0; u_ < 2; u_++) {
            float a0 = A0[r_][u_], a4 = A4[r_][u_];
            float a1 = A1[r_][u_], b1 = B1[r_][u_];
            float a2 = A2[r_][u_], b2 = B2[r_][u_];
            float a3 = A3[r_][u_], b3 = B3[r_][u_];
            float pA = a0 + a4, mA = a0 - a4;
            float s1p = K * (a1 - b1), s1m = K * (a1 + b1);
            float s3p = K * (a3 + b3), s3m = K * (a3 - b3);
            ov[0][u_] = pA + a1 + a2 + a3;
            ov[1][u_] = mA + s1p - b2 - s3p;
            ov[2][u_] = pA - b1 - a2 + b3;
            ov[3][u_] = mA - s1m + b2 + s3m;
            ov[4][u_] = pA - a1 + a2 - a3;
            ov[5][u_] = mA - s1p - b2 + s3p;
            ov[6][u_] = pA + b1 - a2 - b3;
            ov[7][u_] = mA + s1m + b2 - s3m;
        }
        float* dst = outp + (size_t)(r0 + rr + r_) * L_ + u0 + uu;
        #pragma unroll
        for (int p = 0; p < 8; p++)
            *(float2*)(dst + 128 * p) = make_float2(ov[p][0], ov[p][1]);
    }
}

// ---------------- launch ---------------------------------------------------
extern "C" void kernel_launch(void* const* d_in, const int* in_sizes, int n_in,
                              void* d_out, int out_size) {
    const float* q   = (const float*)d_in[0];
    const float* k   = (const float*)d_in[1];
    const float* wr  = (const float*)d_in[4];
    const float* wi  = (const float*)d_in[5];
    const int*   iq  = (const int*)d_in[6];
    const int*   ikv = (const int*)d_in[7];
    float* out = (float*)d_out;

    setup1_k<<<7, 256>>>(iq, ikv);
    setup2_k<<<2208, 256>>>(wr, wi);
    cudaFuncSetAttribute(dft8m_k, cudaFuncAttributeMaxDynamicSharedMemorySize, 51200);
    dft8m_k<<<dim3(32, B_, 2), 256, 51200>>>(q, k);
    cudaFuncSetAttribute(stage23_k, cudaFuncAttributeMaxDynamicSharedMemorySize, 65536);
    stage23_k<<<dim3(H_, B_), 512, 65536>>>();
    cudaFuncSetAttribute(xw_k, cudaFuncAttributeMaxDynamicSharedMemorySize, 49152);
    xw_k<<<dim3(64, 8), 128, 49152>>>();
    cudaFuncSetAttribute(inv8_k, cudaFuncAttributeMaxDynamicSharedMemorySize, 49152);
    inv8_k<<<dim3(4, 512), 256, 49152>>>(out);
}

// round 17
// speedup vs baseline: 1.0926x; 1.0926x over previous
#include <cuda_runtime.h>
#include <math.h>

#define B_    32
#define H_    8
#define E_    64
#define M_    64
#define L_    1024
#define DOUT_ 64
#define HE    512
#define M2    128

// ---------------- device scratch ----------------
__device__ float d_QfP[2][B_ * HE * M2];
__device__ float d_KfP[2][B_ * HE * M2];
__device__ float d_KV[512 * 2 * 2048];
__device__ float d_WTr[8 * 64 * 64 * 64];
__device__ float d_WTi[8 * 64 * 64 * 64];
__device__ float d_X2T[128 * 16384];
__device__ float2 d_sc[L_];

// radix-8 forward twiddles [z][part][u][128 slots]
__device__ float d_T8m[2][2][128][128];
__device__ float d_T8s[2][2][128][128];
__device__ int d_m8v[2][128];
__device__ int d_pgA8v[2][32];
__device__ int d_pgB8v[2][32];
__device__ int d_p2s8[2][64];
__device__ int d_Spad8[2];

// radix-8 inverse tables [slot][u<128]
__device__ float d_IAr[64 * 128], d_IAi[64 * 128];
__device__ float d_IBr[64 * 128], d_IBi[64 * 128];
__device__ int d_slotm_q[64];
__device__ int d_pos2slot_q[64];
__device__ int d_bnd_q[4];

// ---------------- setup1: sc LUT + both metas (one launch) -----------------
__global__ void setup1_k(const int* __restrict__ iq, const int* __restrict__ ikv) {
    __shared__ int mA[64], keys[64], s2p[128];
    const int bx = blockIdx.x, tid = threadIdx.x;
    if (bx < 4) {
        int t = bx * 256 + tid;
        const double C = 6.283185307179586476925286766559 / (double)L_;
        double th = C * (double)t;
        d_sc[t] = make_float2((float)cos(th), (float)sin(th));
        return;
    }
    if (bx == 4) {
        if (tid < 64) mA[tid] = iq[tid];
        __syncthreads();
        if (tid < 64) {
            int m = mA[tid], c = m & 7;
            int cp = (c <= 4) ? c : 8 - c;
            int rank = (cp == 0) ? 0 : (cp == 4) ? 1 : (cp == 1) ? 2 : (cp == 2) ? 3 : 4;
            keys[tid] = rank * 64 + tid;
        }
        __syncthreads();
        if (tid < 64) {
            int key = keys[tid], slot = 0;
            for (int t = 0; t < 64; t++) slot += (keys[t] < key);
            d_slotm_q[slot] = mA[tid];
            d_pos2slot_q[tid] = slot;
        }
        __syncthreads();
        if (tid == 0) {
            int cnt[5] = {0, 0, 0, 0, 0};
            for (int t = 0; t < 64; t++) {
                int cc = mA[t] & 7;
                int cpp = (cc <= 4) ? cc : 8 - cc;
                int rr = (cpp == 0) ? 0 : (cpp == 4) ? 1 : (cpp == 1) ? 2 : (cpp == 2) ? 3 : 4;
                cnt[rr]++;
            }
            d_bnd_q[0] = cnt[0];
            d_bnd_q[1] = cnt[0] + cnt[1];
            d_bnd_q[2] = cnt[0] + cnt[1] + cnt[2];
            d_bnd_q[3] = cnt[0] + cnt[1] + cnt[2] + cnt[3];
        }
        return;
    }
    {
        int z = bx - 5;
        const int* ix = z ? ikv : iq;
        if (tid < 64) mA[tid] = ix[tid];
        __syncthreads();
        if (tid == 0) {
            int cS[64], cnt[5] = {0,0,0,0,0};
            for (int t = 0; t < 64; t++) {
                int c = mA[t] & 7;
                int cp = (c <= 4) ? c : 8 - c;
                cS[t] = cp; cnt[cp]++;
            }
            int pb[5], pe[5], acc = 0;
            for (int c = 0; c < 5; c++) { pb[c] = acc; acc += (cnt[c] + 3) & ~3; pe[c] = acc; }
            d_Spad8[z] = acc;
            for (int s = 0; s < 128; s++) { d_m8v[z][s] = -1; s2p[s] = -1; }
            int fill[5] = {0,0,0,0,0};
            for (int t = 0; t < 64; t++) {
                int s = pb[cS[t]] + fill[cS[t]]++;
                d_m8v[z][s] = mA[t];
                s2p[s] = t;
            }
            const int pAt[5] = {0, 2, 4, 6, 1};
            const int pBt[5] = {0, 3, 5, 7, 1};
            for (int g = 0; g < 32; g++) {
                int s0 = g * 4, A = 0, Bp = 0;
                for (int c = 0; c < 5; c++)
                    if (cnt[c] > 0 && s0 >= pb[c] && s0 < pe[c]) { A = pAt[c]; Bp = pBt[c]; }
                d_pgA8v[z][g] = A;
                d_pgB8v[z][g] = Bp;
            }
            for (int s = 0; s < 128; s++)
                if (s2p[s] >= 0) d_p2s8[z][s2p[s]] = s;
        }
    }
}

// ---------------- setup2: twiddle tables + w transpose (one launch) ---------
__global__ __launch_bounds__(256) void setup2_k(const float* __restrict__ wr_g,
                                                const float* __restrict__ wi_g) {
    __shared__ float tile[32][33];
    const int bx = blockIdx.x, tid = threadIdx.x;
    if (bx < 32) {
        int idx = bx * 256 + tid;
        int j = idx >> 7, u = idx & 127;
        int m = d_slotm_q[j];
        float2 cs = d_sc[(m * u) & (L_ - 1)];
        float g = ((m == 0) || (2 * m == L_)) ? (1.0f / L_) : (2.0f / L_);
        int c = m & 7;
        float sg = (c < 4) ? 1.f : -1.f;
        bool noB = (c == 0) || (c == 4);
        d_IAr[j * 128 + u] =  g * cs.x;
        d_IAi[j * 128 + u] = -g * cs.y;
        d_IBr[j * 128 + u] = noB ? 0.f : (sg * g * cs.y);
        d_IBi[j * 128 + u] = noB ? 0.f : (sg * g * cs.x);
        return;
    }
    if (bx < 160) {
        int r = bx - 32;
        int z = r >> 6;
        int idx = (r & 63) * 256 + tid;
        int u = idx >> 7, s = idx & 127;
        int m = d_m8v[z][s];
        float tmr = 0.f, tsr = 0.f, tmi = 0.f, tsi = 0.f;
        if (m >= 0) {
            float2 cssn = d_sc[(m * u) & (L_ - 1)];
            int c = m & 7;
            float sg = (c <= 4) ? 1.f : -1.f;
            bool noB = (c == 0) || (c == 4);
            tmr = cssn.x;
            tsr = noB ? 0.f : (sg * cssn.y);
            tmi = -cssn.y;
            tsi = noB ? 0.f : (sg * cssn.x);
        }
        d_T8m[z][0][u][s] = tmr;
        d_T8s[z][0][u][s] = tsr;
        d_T8m[z][1][u][s] = tmi;
        d_T8s[z][1][u][s] = tsi;
        return;
    }
    {
        int rr = bx - 160;
        const int ot = (rr & 1) * 32;
        const int mt = ((rr >> 1) & 1) * 32;
        const int e  = (rr >> 2) & 63;
        const int h  = rr >> 8;
        const int r  = tid >> 3;
        const int c4 = (tid & 7) * 4;
        for (int z = 0; z < 2; z++) {
            const float* src = z ? wi_g : wr_g;
            float* dst = z ? d_WTi : d_WTr;
            float4 v = *(const float4*)&src[((size_t)(h * 64 + e) * 64 + ot + r) * 64 + mt + c4];
            tile[r][c4 + 0] = v.x; tile[r][c4 + 1] = v.y;
            tile[r][c4 + 2] = v.z; tile[r][c4 + 3] = v.w;
            __syncthreads();
            float4 o;
            o.x = tile[c4 + 0][r]; o.y = tile[c4 + 1][r];
            o.z = tile[c4 + 2][r]; o.w = tile[c4 + 3][r];
            *(float4*)&dst[((size_t)(h * 64 + mt + r) * 64 + e) * 64 + ot + c4] = o;
            __syncthreads();
        }
    }
}

// ---------------- forward: radix-8 folded DFT, 256 thr, 4x4 tile -----------
#define PLPAD 68
#define PLBUF (8 * 8 * PLPAD)
__global__ __launch_bounds__(256, 3) void dft8m_k(const float* __restrict__ qg,
                                                  const float* __restrict__ kg) {
    const int bx   = blockIdx.x;
    const int tile = bx & 1;
    const int us   = (bx >> 1) & 1;
    const int heT  = bx >> 2;
    const int b    = blockIdx.y;
    const int zin  = blockIdx.z;
    if (tile * 64 >= d_Spad8[zin]) return;

    extern __shared__ float sm[];
    float* PL = sm;
    float* TW = sm + 2 * PLBUF;

    const float* __restrict__ x = zin ? kg : qg;
    float* outp = zin ? d_KfP[us] : d_QfP[us];
    const int he0 = heT * 64;
    const int tid = threadIdx.x;
    const int g   = tid & 15;
    const int cx  = g * 4;
    const int ry  = ((tid >> 4) & 15) * 4;
    const int pgA = d_pgA8v[zin][tile * 16 + g];
    const int pgB = d_pgB8v[zin][tile * 16 + g];
    const float* xb = x + (size_t)b * (L_ * HE) + he0;

    float accR[4][4], accI[4][4];
    #pragma unroll
    for (int i = 0; i < 4; i++)
        #pragma unroll
        for (int j = 0; j < 4; j++) { accR[i][j] = 0.f; accI[i][j] = 0.f; }

    auto load = [&](int ks, int buf) {
        const int u0 = us * 64 + ks * 8;
        if (tid < 128) {
            float* plb = PL + buf * PLBUF;
            const int ul = tid >> 4;
            const int c4 = (tid & 15) * 4;
            const float* p = xb + (size_t)(u0 + ul) * HE + c4;
            float4 xs[8];
            #pragma unroll
            for (int pp = 0; pp < 8; pp++)
                xs[pp] = *(const float4*)(p + (size_t)pp * 128 * HE);
            float4 pl8[8];
            const float KK = 0.70710678118654752440f;
            #pragma unroll
            for (int q = 0; q < 4; q++) {
                float x0 = (&xs[0].x)[q], x1 = (&xs[1].x)[q], x2 = (&xs[2].x)[q], x3 = (&xs[3].x)[q];
                float x4 = (&xs[4].x)[q], x5 = (&xs[5].x)[q], x6 = (&xs[6].x)[q], x7 = (&xs[7].x)[q];
                float e0 = x0 + x4, e1 = x1 + x5, e2 = x2 + x6, e3 = x3 + x7;
                float o0 = x0 - x4, o1 = x1 - x5, o2 = x2 - x6, o3 = x3 - x7;
                float g0 = e0 + e2, g1 = e1 + e3;
                float t1 = o1 - o3, t2 = o1 + o3;
                float kt1 = KK * t1, kt2 = KK * t2;
                (&pl8[0].x)[q] = g0 + g1;
                (&pl8[1].x)[q] = g0 - g1;
                (&pl8[2].x)[q] = o0 + kt1;
                (&pl8[3].x)[q] = -kt2 - o2;
                (&pl8[4].x)[q] = e0 - e2;
                (&pl8[5].x)[q] = e3 - e1;
                (&pl8[6].x)[q] = o0 - kt1;
                (&pl8[7].x)[q] = o2 - kt2;
            }
            #pragma unroll
            for (int pl = 0; pl < 8; pl++)
                *(float4*)&plb[(ul * 8 + pl) * PLPAD + c4] = pl8[pl];
        } else {
            float* twb = TW + buf * 2048;
            #pragma unroll
            for (int r = 0; r < 4; r++) {
                int f = (tid - 128) + 128 * r;
                int uu  = f >> 6;
                int wh  = (f >> 4) & 3;
                int c4t = (f & 15) * 4;
                const float* srcT;
                if (wh == 0)      srcT = &d_T8m[zin][0][u0 + uu][tile * 64];
                else if (wh == 1) srcT = &d_T8s[zin][0][u0 + uu][tile * 64];
                else if (wh == 2) srcT = &d_T8m[zin][1][u0 + uu][tile * 64];
                else              srcT = &d_T8s[zin][1][u0 + uu][tile * 64];
                *(float4*)&twb[(uu * 4 + wh) * 64 + c4t] = *(const float4*)(srcT + c4t);
            }
        }
    };

    load(0, 0);
    __syncthreads();
    #pragma unroll 1
    for (int ks = 0; ks < 8; ks++) {
        int buf = ks & 1;
        if (ks + 1 < 8) load(ks + 1, buf ^ 1);
        float* plb = PL + buf * PLBUF;
        float* twb = TW + buf * 2048;
        #pragma unroll
        for (int u = 0; u < 8; u++) {
            float av[4], bw[4], tmr[4], tsr[4], tmi[4], tsi[4];
            *(float4*)&av[0] = *(float4*)&plb[(u * 8 + pgA) * PLPAD + ry];
            *(float4*)&bw[0] = *(float4*)&plb[(u * 8 + pgB) * PLPAD + ry];
            *(float4*)&tmr[0] = *(float4*)&twb[(u * 4 + 0) * 64 + cx];
            *(float4*)&tsr[0] = *(float4*)&twb[(u * 4 + 1) * 64 + cx];
            *(float4*)&tmi[0] = *(float4*)&twb[(u * 4 + 2) * 64 + cx];
            *(float4*)&tsi[0] = *(float4*)&twb[(u * 4 + 3) * 64 + cx];
            #pragma unroll
            for (int i = 0; i < 4; i++)
                #pragma unroll
                for (int j = 0; j < 4; j++) {
                    accR[i][j] += av[i] * tmr[j] + bw[i] * tsr[j];
                    accI[i][j] += av[i] * tmi[j] + bw[i] * tsi[j];
                }
        }
        __syncthreads();
    }

    float* OUT = sm;
    #pragma unroll
    for (int i = 0; i < 4; i++) {
        int row = ry + i;
        int rsw = (row >> 2) & 2;
        #pragma unroll
        for (int j = 0; j < 4; j++) {
            int cR = cx + j;
            OUT[row * 128 + (cR ^ ((cR >> 5) & 1) ^ rsw)] = accR[i][j];
            int cI = 64 + cx + j;
            OUT[row * 128 + (cI ^ ((cI >> 5) & 1) ^ rsw)] = accI[i][j];
        }
    }
    __syncthreads();
    {
        int c = tid & 127;
        int rh = tid >> 7;
        int sl = d_p2s8[zin][c & 63];
        if ((sl >> 6) == tile) {
            int srcCol = (c < 64) ? (sl & 63) : (64 + (sl & 63));
            srcCol ^= (srcCol >> 5) & 1;
            float* dstc = outp + ((size_t)b * HE + he0 + rh * 32) * M2 + c;
            #pragma unroll 8
            for (int r = 0; r < 32; r++) {
                int row = rh * 32 + r;
                dstc[(size_t)r * M2] = OUT[row * 128 + (srcCol ^ ((row >> 2) & 2))];
            }
        }
    }
}

// ---------------- stage2+3: qk GEMM + tanh + kv GEMM (512 thr) -------------
__global__ __launch_bounds__(512) void stage23_k() {
    extern __shared__ float sm[];
    float* Qs  = sm;            // [64][128]
    float* Ks  = sm + 8192;
    float* qkr = sm;            // alias over Qs (after sync)
    float* qki = sm + 4096;

    const int h = blockIdx.x, b = blockIdx.y;
    const int tid = threadIdx.x;

    const size_t off4 = (((size_t)b * HE + h * E_) * M2) / 4;
    for (int i = tid; i < E_ * M2 / 4; i += 512) {
        float4 a0 = ((const float4*)d_QfP[0])[off4 + i];
        float4 a1 = ((const float4*)d_QfP[1])[off4 + i];
        ((float4*)Qs)[i] = make_float4(a0.x + a1.x, a0.y + a1.y,
                                       a0.z + a1.z, a0.w + a1.w);
        float4 c0 = ((const float4*)d_KfP[0])[off4 + i];
        float4 c1 = ((const float4*)d_KfP[1])[off4 + i];
        ((float4*)Ks)[i] = make_float4(c0.x + c1.x, c0.y + c1.y,
                                       c0.z + c1.z, c0.w + c1.w);
    }
    __syncthreads();

    const int x0 = (tid & 15) * 4;
    const int yg = tid >> 4;         // 0..31
    {
        int y0 = yg * 2;
        float ar[2][4], ai[2][4];
        #pragma unroll
        for (int yy = 0; yy < 2; yy++)
            #pragma unroll
            for (int xx = 0; xx < 4; xx++) { ar[yy][xx] = 0.f; ai[yy][xx] = 0.f; }
        #pragma unroll 4
        for (int e = 0; e < 64; e++) {
            float4 q4r = *(float4*)&Qs[e * 128 + x0];
            float4 q4i = *(float4*)&Qs[e * 128 + 64 + x0];
            float2 k2r = *(float2*)&Ks[e * 128 + y0];
            float2 k2i = *(float2*)&Ks[e * 128 + 64 + y0];
            float qrv[4] = {q4r.x,q4r.y,q4r.z,q4r.w};
            float qiv[4] = {q4i.x,q4i.y,q4i.z,q4i.w};
            float krv[2] = {k2r.x,k2r.y};
            float kiv[2] = {k2i.x,k2i.y};
            #pragma unroll
            for (int yy = 0; yy < 2; yy++)
                #pragma unroll
                for (int xx = 0; xx < 4; xx++) {
                    ar[yy][xx] += qrv[xx]*krv[yy] - qiv[xx]*kiv[yy];
                    ai[yy][xx] += qrv[xx]*kiv[yy] + qiv[xx]*krv[yy];
                }
        }
        __syncthreads();
        #pragma unroll
        for (int yy = 0; yy < 2; yy++)
            #pragma unroll
            for (int xx = 0; xx < 4; xx++) {
                qkr[(y0 + yy) * 64 + x0 + xx] = tanhf(ar[yy][xx]);
                qki[(y0 + yy) * 64 + x0 + xx] = tanhf(ai[yy][xx]);
            }
    }
    __syncthreads();

    {
        int e0 = yg * 2;
        float cr[2][4], ci[2][4];
        #pragma unroll
        for (int ee = 0; ee < 2; ee++)
            #pragma unroll
            for (int xx = 0; xx < 4; xx++) { cr[ee][xx] = 0.f; ci[ee][xx] = 0.f; }
        #pragma unroll 4
        for (int y = 0; y < 64; y++) {
            float4 q4r = *(float4*)&qkr[y * 64 + x0];
            float4 q4i = *(float4*)&qki[y * 64 + x0];
            float qrv[4] = {q4r.x,q4r.y,q4r.z,q4r.w};
            float qiv[4] = {q4i.x,q4i.y,q4i.z,q4i.w};
            float krv[2], kiv[2];
            #pragma unroll
            for (int ee = 0; ee < 2; ee++) {
                krv[ee] = Ks[(e0 + ee) * 128 + y];
                kiv[ee] = Ks[(e0 + ee) * 128 + 64 + y];
            }
            #pragma unroll
            for (int ee = 0; ee < 2; ee++)
                #pragma unroll
                for (int xx = 0; xx < 4; xx++) {
                    cr[ee][xx] += qrv[xx]*krv[ee] - qiv[xx]*kiv[ee];
                    ci[ee][xx] += qrv[xx]*kiv[ee] + qiv[xx]*krv[ee];
                }
        }
        #pragma unroll
        for (int xx = 0; xx < 4; xx++) {
            size_t base = ((size_t)(h * 64 + x0 + xx) * 2) * 2048 + b * 64 + e0;
            *(float2*)&d_KV[base]        = make_float2(cr[0][xx], cr[1][xx]);
            *(float2*)&d_KV[base + 2048] = make_float2(ci[0][xx], ci[1][xx]);
        }
    }
}

// ---------------- stage4: per-(h,mode) pointwise complex GEMM --------------
__global__ __launch_bounds__(128) void xw_k() {
    extern __shared__ float sm[];
    float* kvS = sm;         // [e][c][b]
    float* wS  = sm + 4096;  // [e][c][o]
    const int x = blockIdx.x, h = blockIdx.y;
    const int tid = threadIdx.x;

    {
        const float4* kb = (const float4*)(d_KV + ((size_t)(h * 64 + x) * 2) * 2048);
        #pragma unroll
        for (int r = 0; r < 8; r++) {
            int idx4 = tid + 128 * r;
            float4 v = kb[idx4];
            int e4 = idx4 & 15, bb = (idx4 >> 4) & 31, c = idx4 >> 9;
            #pragma unroll
            for (int j = 0; j < 4; j++)
                kvS[((e4 * 4 + j) * 2 + c) * 32 + bb] = (&v.x)[j];
        }
        const float4* wrb = (const float4*)(d_WTr + (size_t)(h * 64 + x) * 4096);
        const float4* wib = (const float4*)(d_WTi + (size_t)(h * 64 + x) * 4096);
        #pragma unroll
        for (int r = 0; r < 8; r++) {
            int idx4 = tid + 128 * r;
            int e = idx4 >> 4, o4 = idx4 & 15;
            *(float4*)&wS[(e * 2 + 0) * 64 + o4 * 4] = wrb[idx4];
            *(float4*)&wS[(e * 2 + 1) * 64 + o4 * 4] = wib[idx4];
        }
    }
    __syncthreads();

    const int b0 = (tid >> 4) * 4;
    const int o0 = (tid & 15) * 4;
    float cr[4][4], ci[4][4];
    #pragma unroll
    for (int i = 0; i < 4; i++)
        #pragma unroll
        for (int j = 0; j < 4; j++) { cr[i][j] = 0.f; ci[i][j] = 0.f; }

    #pragma unroll 4
    for (int e = 0; e < 64; e++) {
        float4 kr4 = *(float4*)&kvS[(e * 2 + 0) * 32 + b0];
        float4 ki4 = *(float4*)&kvS[(e * 2 + 1) * 32 + b0];
        float4 wr4 = *(float4*)&wS[(e * 2 + 0) * 64 + o0];
        float4 wi4 = *(float4*)&wS[(e * 2 + 1) * 64 + o0];
        float kr[4] = {kr4.x,kr4.y,kr4.z,kr4.w};
        float ki[4] = {ki4.x,ki4.y,ki4.z,ki4.w};
        float wr[4] = {wr4.x,wr4.y,wr4.z,wr4.w};
        float wi[4] = {wi4.x,wi4.y,wi4.z,wi4.w};
        #pragma unroll
        for (int i = 0; i < 4; i++)
            #pragma unroll
            for (int j = 0; j < 4; j++) {
                cr[i][j] += kr[i]*wr[j] - ki[i]*wi[j];
                ci[i][j] += kr[i]*wi[j] + ki[i]*wr[j];
            }
    }
    __syncthreads();

    const float S = 1.0f / 262144.0f;
    #pragma unroll
    for (int i = 0; i < 4; i++) {
        *(float4*)&wS[(0 * 32 + b0 + i) * 64 + o0] =
            make_float4(cr[i][0]*S, cr[i][1]*S, cr[i][2]*S, cr[i][3]*S);
        *(float4*)&wS[(1 * 32 + b0 + i) * 64 + o0] =
            make_float4(ci[i][0]*S, ci[i][1]*S, ci[i][2]*S, ci[i][3]*S);
    }
    __syncthreads();

    int slot = d_pos2slot_q[x];
    #pragma unroll
    for (int r = 0; r < 8; r++) {
        int idx4 = tid + 128 * r;
        int c = idx4 >> 9, bb = (idx4 >> 4) & 31, o4 = idx4 & 15;
        *(float4*)&d_X2T[(size_t)(2 * slot + c) * 16384 + (bb * 8 + h) * 64 + o4 * 4] =
            ((float4*)wS)[idx4];
    }
}

// ---------------- inverse: radix-8 folded irfft (64 rows/block) -------------
__global__ __launch_bounds__(256) void inv8_k(float* __restrict__ outp) {
    extern __shared__ float sm[];
    float* Ys = sm;              // [64 rows][128]
    float* Ar = sm + 8192;       // [64 slots][32 u]
    float* Ai = sm + 10240;
    float* Br = sm + 12288;
    float* Bi = sm + 14336;
    const int u0 = blockIdx.x * 32;
    const int r0 = blockIdx.y * 64;
    const int tid = threadIdx.x;

    for (int i = tid; i < 2048; i += 256) {
        int p = i >> 4, r4 = (i & 15) * 4;
        float4 v = *(const float4*)&d_X2T[(size_t)p * 16384 + r0 + r4];
        Ys[(r4 + 0) * 128 + p] = v.x;
        Ys[(r4 + 1) * 128 + p] = v.y;
        Ys[(r4 + 2) * 128 + p] = v.z;
        Ys[(r4 + 3) * 128 + p] = v.w;
    }
    for (int i = tid; i < 512; i += 256) {
        int s = i >> 3, f = (i & 7) * 4;
        *(float4*)&Ar[s * 32 + f] = *(const float4*)&d_IAr[s * 128 + u0 + f];
        *(float4*)&Ai[s * 32 + f] = *(const float4*)&d_IAi[s * 128 + u0 + f];
        *(float4*)&Br[s * 32 + f] = *(const float4*)&d_IBr[s * 128 + u0 + f];
        *(float4*)&Bi[s * 32 + f] = *(const float4*)&d_IBi[s * 128 + u0 + f];
    }
    __syncthreads();

    const int rr = (tid >> 4) * 4;
    const int uu = (tid & 15) * 2;
    float A0[4][2] = {}, A4[4][2] = {};
    float A1[4][2] = {}, B1[4][2] = {};
    float A2[4][2] = {}, B2[4][2] = {};
    float A3[4][2] = {}, B3[4][2] = {};

    const int n0 = d_bnd_q[0], n4 = d_bnd_q[1], n1 = d_bnd_q[2], n2 = d_bnd_q[3];

#define IACC_A(S, A) { \
    float2 a2 = *(float2*)&Ar[(S) * 32 + uu]; \
    float2 i2 = *(float2*)&Ai[(S) * 32 + uu]; \
    _Pragma("unroll") \
    for (int r_ = 0; r_ < 4; r_++) { \
        float2 y = *(float2*)&Ys[(rr + r_) * 128 + 2 * (S)]; \
        A[r_][0] += y.x * a2.x + y.y * i2.x; \
        A[r_][1] += y.x * a2.y + y.y * i2.y; \
    } }

#define IACC_AB(S, A, Bm) { \
    float2 a2 = *(float2*)&Ar[(S) * 32 + uu]; \
    float2 i2 = *(float2*)&Ai[(S) * 32 + uu]; \
    float2 b2 = *(float2*)&Br[(S) * 32 + uu]; \
    float2 c2 = *(float2*)&Bi[(S) * 32 + uu]; \
    _Pragma("unroll") \
    for (int r_ = 0; r_ < 4; r_++) { \
        float2 y = *(float2*)&Ys[(rr + r_) * 128 + 2 * (S)]; \
        A[r_][0]  += y.x * a2.x + y.y * i2.x; \
        A[r_][1]  += y.x * a2.y + y.y * i2.y; \
        Bm[r_][0] += y.x * b2.x + y.y * c2.x; \
        Bm[r_][1] += y.x * b2.y + y.y * c2.y; \
    } }

    for (int s = 0;  s < n0; s++) IACC_A(s, A0);
    for (int s = n0; s < n4; s++) IACC_A(s, A4);
    for (int s = n4; s < n1; s++) IACC_AB(s, A1, B1);
    for (int s = n1; s < n2; s++) IACC_AB(s, A2, B2);
    for (int s = n2; s < 64; s++) IACC_AB(s, A3, B3);

#undef IACC_A
#undef IACC_AB

    const float K = 0.70710678118654752440f;
    #pragma unroll
    for (int r_ = 0; r_ < 4; r_++) {
        float ov[8][2];
        #pragma unroll
        for (int u_ = 0; u_ < 2; u_++) {
            float a0 = A0[r_][u_], a4 = A4[r_][u_];
            float a1 = A1[r_][u_], b1 = B1[r_][u_];
            float a2 = A2[r_][u_], b2 = B2[r_][u_];
            float a3 = A3[r_][u_], b3 = B3[r_][u_];
            float pA = a0 + a4, mA = a0 - a4;
            float s1p = K * (a1 - b1), s1m = K * (a1 + b1);
            float s3p = K * (a3 + b3), s3m = K * (a3 - b3);
            ov[0][u_] = pA + a1 + a2 + a3;
            ov[1][u_] = mA + s1p - b2 - s3p;
            ov[2][u_] = pA - b1 - a2 + b3;
            ov[3][u_] = mA - s1m + b2 + s3m;
            ov[4][u_] = pA - a1 + a2 - a3;
            ov[5][u_] = mA - s1p - b2 + s3p;
            ov[6][u_] = pA + b1 - a2 - b3;
            ov[7][u_] = mA + s1m + b2 - s3m;
        }
        float* dst = outp + (size_t)(r0 + rr + r_) * L_ + u0 + uu;
        #pragma unroll
        for (int p = 0; p < 8; p++)
            *(float2*)(dst + 128 * p) = make_float2(ov[p][0], ov[p][1]);
    }
}

// ---------------- launch ---------------------------------------------------
extern "C" void kernel_launch(void* const* d_in, const int* in_sizes, int n_in,
                              void* d_out, int out_size) {
    const float* q   = (const float*)d_in[0];
    const float* k   = (const float*)d_in[1];
    const float* wr  = (const float*)d_in[4];
    const float* wi  = (const float*)d_in[5];
    const int*   iq  = (const int*)d_in[6];
    const int*   ikv = (const int*)d_in[7];
    float* out = (float*)d_out;

    setup1_k<<<7, 256>>>(iq, ikv);
    setup2_k<<<2208, 256>>>(wr, wi);
    cudaFuncSetAttribute(dft8m_k, cudaFuncAttributeMaxDynamicSharedMemorySize, 51200);
    dft8m_k<<<dim3(32, B_, 2), 256, 51200>>>(q, k);
    cudaFuncSetAttribute(stage23_k, cudaFuncAttributeMaxDynamicSharedMemorySize, 65536);
    stage23_k<<<dim3(H_, B_), 512, 65536>>>();
    cudaFuncSetAttribute(xw_k, cudaFuncAttributeMaxDynamicSharedMemorySize, 49152);
    xw_k<<<dim3(64, 8), 128, 49152>>>();
    cudaFuncSetAttribute(inv8_k, cudaFuncAttributeMaxDynamicSharedMemorySize, 65536);
    inv8_k<<<dim3(4, 256), 256, 65536>>>(out);
}